// round 2
// baseline (speedup 1.0000x reference)
#include <cuda_runtime.h>

#define D_MODEL 1024
#define SEQLEN  2048
#define BATCH   4
#define NHEADS  16
#define HDIM    64
#define MROWS   (BATCH * SEQLEN)   /* 8192 */
#define INV_TAU (1.0f / 0.07f)

typedef unsigned long long ull;

// Scratch (allocation-free rule: __device__ globals)
__device__ float g_Qp[MROWS * D_MODEL];
__device__ float g_Kp[MROWS * D_MODEL];
__device__ float g_Vp[MROWS * D_MODEL];
__device__ float g_Ao[MROWS * D_MODEL];

// ---- packed f32x2 helpers (ptxas never emits FFMA2 from C++) ----
__device__ __forceinline__ void ffma2(ull& d, ull a, ull b) {
    asm("fma.rn.f32x2 %0, %1, %2, %0;" : "+l"(d) : "l"(a), "l"(b));
}
__device__ __forceinline__ ull fmul2(ull a, ull b) {
    ull r; asm("mul.rn.f32x2 %0, %1, %2;" : "=l"(r) : "l"(a), "l"(b)); return r;
}
__device__ __forceinline__ ull pack2(float x, float y) {
    ull r; asm("mov.b64 %0, {%1, %2};" : "=l"(r) : "f"(x), "f"(y)); return r;
}
__device__ __forceinline__ float2 upk2(ull v) {
    float2 f; asm("mov.b64 {%0, %1}, %2;" : "=f"(f.x), "=f"(f.y) : "l"(v)); return f;
}
__device__ __forceinline__ float hadd2(ull v) {
    float2 f = upk2(v); return f.x + f.y;
}

// ---------------------------------------------------------------------------
// GEMM: C[M,N] = A[M,K] @ W[N,K]^T + bias[N]
// 128x128 tile, BK=16, 256 threads, 8x8 per thread, k-paired FFMA2.
// Lanes of each 64-bit accumulator hold even/odd-k partial sums.
// ---------------------------------------------------------------------------
__global__ __launch_bounds__(256, 1) void gemm_bias_kernel(
    const float* __restrict__ A, const float* __restrict__ W,
    const float* __restrict__ bias, float* __restrict__ C,
    int M, int N, int K)
{
    __shared__ ull As2[128 * 9];   // [m][k-pair], stride 9 (pad)
    __shared__ ull Bs2[128 * 8];   // [n][k-pair], XOR-swizzled by (n>>3)&7

    const int tid  = threadIdx.x;
    const int brow = blockIdx.y * 128;
    const int bcol = blockIdx.x * 128;
    const int ty   = tid >> 4;          // 0..15 -> rows ty*8..+7
    const int tx   = tid & 15;          // 0..15 -> cols tx*8..+7

    // A loader: row = tid>>1, k-half = tid&1 (8 floats each)
    const int alr = tid >> 1;
    const int alh = tid & 1;
    // W loader: scattered rows so smem writes are conflict-light
    const int wlr = ((tid & 15) << 3) | ((tid >> 4) & 7);
    const int wlh = tid >> 7;

    const float* Ap = A + (size_t)(brow + alr) * K + alh * 8;
    const float* Wp = W + (size_t)(bcol + wlr) * K + wlh * 8;

    ull acc[8][8];
#pragma unroll
    for (int i = 0; i < 8; i++)
#pragma unroll
        for (int j = 0; j < 8; j++) acc[i][j] = 0ull;

    const int bswz = (wlr >> 3) & 7;

    for (int k0 = 0; k0 < K; k0 += 16) {
        float4 a0 = *(const float4*)(Ap + k0);
        float4 a1 = *(const float4*)(Ap + k0 + 4);
        float4 w0 = *(const float4*)(Wp + k0);
        float4 w1 = *(const float4*)(Wp + k0 + 4);
        __syncthreads();
        {
            ull* ap = &As2[alr * 9 + alh * 4];
            ap[0] = pack2(a0.x, a0.y); ap[1] = pack2(a0.z, a0.w);
            ap[2] = pack2(a1.x, a1.y); ap[3] = pack2(a1.z, a1.w);
            ull* bp = &Bs2[wlr * 8];
            int p0 = wlh * 4;
            bp[(p0 + 0) ^ bswz] = pack2(w0.x, w0.y);
            bp[(p0 + 1) ^ bswz] = pack2(w0.z, w0.w);
            bp[(p0 + 2) ^ bswz] = pack2(w1.x, w1.y);
            bp[(p0 + 3) ^ bswz] = pack2(w1.z, w1.w);
        }
        __syncthreads();
#pragma unroll
        for (int pk = 0; pk < 8; pk++) {
            ull a2[8], b2[8];
#pragma unroll
            for (int i = 0; i < 8; i++)
                a2[i] = As2[(ty * 8 + i) * 9 + pk];
#pragma unroll
            for (int j = 0; j < 8; j++)
                b2[j] = Bs2[(tx * 8 + j) * 8 + (pk ^ (tx & 7))];
#pragma unroll
            for (int i = 0; i < 8; i++)
#pragma unroll
                for (int j = 0; j < 8; j++)
                    ffma2(acc[i][j], a2[i], b2[j]);
        }
    }

    float bv[8];
    *(float4*)&bv[0] = *(const float4*)(bias + bcol + tx * 8);
    *(float4*)&bv[4] = *(const float4*)(bias + bcol + tx * 8 + 4);
#pragma unroll
    for (int i = 0; i < 8; i++) {
        float* Cp = C + (size_t)(brow + ty * 8 + i) * N + bcol + tx * 8;
        float4 o0, o1;
        o0.x = hadd2(acc[i][0]) + bv[0]; o0.y = hadd2(acc[i][1]) + bv[1];
        o0.z = hadd2(acc[i][2]) + bv[2]; o0.w = hadd2(acc[i][3]) + bv[3];
        o1.x = hadd2(acc[i][4]) + bv[4]; o1.y = hadd2(acc[i][5]) + bv[5];
        o1.z = hadd2(acc[i][6]) + bv[6]; o1.w = hadd2(acc[i][7]) + bv[7];
        *(float4*)Cp       = o0;
        *(float4*)(Cp + 4) = o1;
    }
}

// ---------------------------------------------------------------------------
// Per-head L2 normalize
// ---------------------------------------------------------------------------
__global__ __launch_bounds__(256) void l2norm_kernel(float* __restrict__ X, int nchunks)
{
    int gid  = blockIdx.x * blockDim.x + threadIdx.x;
    int warp = gid >> 5;
    int lane = gid & 31;
    if (warp >= nchunks) return;
    float* p = X + (size_t)warp * 64 + lane * 2;
    float2 v = *(float2*)p;
    float ss = v.x * v.x + v.y * v.y;
#pragma unroll
    for (int m = 16; m > 0; m >>= 1)
        ss += __shfl_xor_sync(0xffffffffu, ss, m);
    float inv = 1.0f / fmaxf(sqrtf(ss), 1e-12f);
    v.x *= inv; v.y *= inv;
    *(float2*)p = v;
}

// ---------------------------------------------------------------------------
// Flash attention, FFMA2 (k-paired) version.
// Smem tiles stored as 64-bit pairs with XOR swizzle (p ^ (row>>2 & 15)).
// Q: [m][d-pair], K: [n][d-pair] (reused for P: [m][k-pair]),
// V: TRANSPOSED [c][k-pair] so the PV loop is also k-paired.
// ---------------------------------------------------------------------------
__global__ __launch_bounds__(256) void attn_kernel(
    const float* __restrict__ Q, const float* __restrict__ K,
    const float* __restrict__ V, float* __restrict__ O)
{
    __shared__ ull Qs2[64 * 32];
    __shared__ ull KPs2[64 * 32];   // K tile, then reused as P
    __shared__ ull Vt2[64 * 32];    // transposed V: row=c, col=k-pair

    const int tid = threadIdx.x;
    const int qt  = blockIdx.x;
    const int bh  = blockIdx.y;
    const int b   = bh >> 4, h = bh & 15;
    const int base = (b * SEQLEN) * D_MODEL + h * HDIM;
    const int ty = tid >> 4, tx = tid & 15;
    const int r0 = ty * 4;
    const int n0 = tx * 4;

    // Load Q tile (scaled by 1/tau), swizzled pairs
#pragma unroll
    for (int i = 0; i < 4; i++) {
        int idx = tid + i * 256;
        int r = idx >> 4, c4 = idx & 15;
        float4 v = *(const float4*)(Q + base + (qt * 64 + r) * D_MODEL + c4 * 4);
        int swz = (r >> 2) & 15;
        ull* qp = &Qs2[r * 32];
        qp[(c4 * 2)     ^ swz] = pack2(v.x * INV_TAU, v.y * INV_TAU);
        qp[(c4 * 2 + 1) ^ swz] = pack2(v.z * INV_TAU, v.w * INV_TAU);
    }

    float m_i[4], l_i[4];
    ull o2[4][4];
#pragma unroll
    for (int i = 0; i < 4; i++) {
        m_i[i] = -1e30f;
        l_i[i] = 0.f;
#pragma unroll
        for (int c = 0; c < 4; c++) o2[i][c] = 0ull;
    }

    float* Vsf = (float*)Vt2;

    for (int kt = 0; kt < SEQLEN / 64; kt++) {
        __syncthreads();   // previous PV readers done before overwriting K/V
#pragma unroll
        for (int i = 0; i < 4; i++) {
            int idx = tid + i * 256;
            int r = idx >> 4, c4 = idx & 15;
            float4 kv = *(const float4*)(K + base + (kt * 64 + r) * D_MODEL + c4 * 4);
            int swz = (r >> 2) & 15;
            ull* kp = &KPs2[r * 32];
            kp[(c4 * 2)     ^ swz] = pack2(kv.x, kv.y);
            kp[(c4 * 2 + 1) ^ swz] = pack2(kv.z, kv.w);
            float4 vv = *(const float4*)(V + base + (kt * 64 + r) * D_MODEL + c4 * 4);
            // transpose into Vt2: element (k=r, c=4*c4+cc)
            int ph = r >> 1, hf = r & 1;
#pragma unroll
            for (int cc = 0; cc < 4; cc++) {
                int c = c4 * 4 + cc;
                float val = (cc == 0) ? vv.x : (cc == 1) ? vv.y : (cc == 2) ? vv.z : vv.w;
                Vsf[(c * 32 + (ph ^ ((c >> 2) & 15))) * 2 + hf] = val;
            }
        }
        __syncthreads();

        // S = (Q/tau) @ K^T, k-paired
        ull s2[4][4];
#pragma unroll
        for (int i = 0; i < 4; i++)
#pragma unroll
            for (int j = 0; j < 4; j++) s2[i][j] = 0ull;

#pragma unroll 8
        for (int p = 0; p < 32; p++) {
            ull q2[4], k2[4];
#pragma unroll
            for (int i = 0; i < 4; i++) q2[i] = Qs2[(r0 + i) * 32 + (p ^ ty)];
#pragma unroll
            for (int j = 0; j < 4; j++) k2[j] = KPs2[(n0 + j) * 32 + (p ^ tx)];
#pragma unroll
            for (int i = 0; i < 4; i++)
#pragma unroll
                for (int j = 0; j < 4; j++)
                    ffma2(s2[i][j], q2[i], k2[j]);
        }
        __syncthreads();   // K reads done before P overwrites buffer

        // Online softmax; write P (paired) into KPs2
#pragma unroll
        for (int i = 0; i < 4; i++) {
            float s0 = hadd2(s2[i][0]), s1 = hadd2(s2[i][1]);
            float s0b = hadd2(s2[i][2]), s1b = hadd2(s2[i][3]);
            float rmax = fmaxf(fmaxf(s0, s1), fmaxf(s0b, s1b));
            rmax = fmaxf(rmax, __shfl_xor_sync(0xffffffffu, rmax, 1));
            rmax = fmaxf(rmax, __shfl_xor_sync(0xffffffffu, rmax, 2));
            rmax = fmaxf(rmax, __shfl_xor_sync(0xffffffffu, rmax, 4));
            rmax = fmaxf(rmax, __shfl_xor_sync(0xffffffffu, rmax, 8));
            float mn = fmaxf(m_i[i], rmax);
            float p0 = __expf(s0 - mn);
            float p1 = __expf(s1 - mn);
            float p2 = __expf(s0b - mn);
            float p3 = __expf(s1b - mn);
            float rs = p0 + p1 + p2 + p3;
            rs += __shfl_xor_sync(0xffffffffu, rs, 1);
            rs += __shfl_xor_sync(0xffffffffu, rs, 2);
            rs += __shfl_xor_sync(0xffffffffu, rs, 4);
            rs += __shfl_xor_sync(0xffffffffu, rs, 8);
            float sc = __expf(m_i[i] - mn);
            l_i[i] = l_i[i] * sc + rs;
            m_i[i] = mn;
            ull sc2 = pack2(sc, sc);
#pragma unroll
            for (int c = 0; c < 4; c++) o2[i][c] = fmul2(o2[i][c], sc2);
            ull* pp = &KPs2[(r0 + i) * 32];
            pp[(tx * 2)     ^ ty] = pack2(p0, p1);
            pp[(tx * 2 + 1) ^ ty] = pack2(p2, p3);
        }
        __syncthreads();

        // O += P @ V, k-paired (V transposed in smem)
#pragma unroll 8
        for (int p = 0; p < 32; p++) {
            ull p2r[4], v2[4];
#pragma unroll
            for (int i = 0; i < 4; i++) p2r[i] = KPs2[(r0 + i) * 32 + (p ^ ty)];
#pragma unroll
            for (int cc = 0; cc < 4; cc++) v2[cc] = Vt2[(n0 + cc) * 32 + (p ^ tx)];
#pragma unroll
            for (int i = 0; i < 4; i++)
#pragma unroll
                for (int cc = 0; cc < 4; cc++)
                    ffma2(o2[i][cc], p2r[i], v2[cc]);
        }
    }

#pragma unroll
    for (int i = 0; i < 4; i++) {
        float inv = 1.0f / l_i[i];
        float4 r;
        r.x = hadd2(o2[i][0]) * inv;
        r.y = hadd2(o2[i][1]) * inv;
        r.z = hadd2(o2[i][2]) * inv;
        r.w = hadd2(o2[i][3]) * inv;
        *(float4*)(O + base + (qt * 64 + r0 + i) * D_MODEL + tx * 4) = r;
    }
}

// ---------------------------------------------------------------------------
extern "C" void kernel_launch(void* const* d_in, const int* in_sizes, int n_in,
                              void* d_out, int out_size)
{
    const float* q  = (const float*)d_in[0];
    const float* k  = (const float*)d_in[1];
    const float* v  = (const float*)d_in[2];
    const float* Wq = (const float*)d_in[3];
    const float* bq = (const float*)d_in[4];
    const float* Wk = (const float*)d_in[5];
    const float* bk = (const float*)d_in[6];
    const float* Wv = (const float*)d_in[7];
    const float* bv = (const float*)d_in[8];
    const float* Wo = (const float*)d_in[9];
    const float* bo = (const float*)d_in[10];
    float* out = (float*)d_out;

    float *Qp, *Kp, *Vp, *Ao;
    cudaGetSymbolAddress((void**)&Qp, g_Qp);
    cudaGetSymbolAddress((void**)&Kp, g_Kp);
    cudaGetSymbolAddress((void**)&Vp, g_Vp);
    cudaGetSymbolAddress((void**)&Ao, g_Ao);

    dim3 ggrid(D_MODEL / 128, MROWS / 128);   // (8, 64)

    gemm_bias_kernel<<<ggrid, 256>>>(q, Wq, bq, Qp, MROWS, D_MODEL, D_MODEL);
    gemm_bias_kernel<<<ggrid, 256>>>(k, Wk, bk, Kp, MROWS, D_MODEL, D_MODEL);
    gemm_bias_kernel<<<ggrid, 256>>>(v, Wv, bv, Vp, MROWS, D_MODEL, D_MODEL);

    const int nchunks = MROWS * NHEADS;       // 131072
    l2norm_kernel<<<nchunks / 8, 256>>>(Qp, nchunks);
    l2norm_kernel<<<nchunks / 8, 256>>>(Kp, nchunks);

    attn_kernel<<<dim3(SEQLEN / 64, BATCH * NHEADS), 256>>>(Qp, Kp, Vp, Ao);

    gemm_bias_kernel<<<ggrid, 256>>>(Ao, Wo, bo, out, MROWS, D_MODEL, D_MODEL);
}